// round 8
// baseline (speedup 1.0000x reference)
#include <cuda_runtime.h>
#include <cstdint>

#define NN   50000
#define EE   800000
#define DIM  96
#define KD   192   // [agg | h] concatenated K
#define ND   96
#define LDIM 64
#define NREL 3
#define TILE_M 128

#define SCAN_M   (NREL * NN)                      // 150000 bins
#define SCAN_TILE 1024
#define SCAN_NT  ((SCAN_M + SCAN_TILE - 1) / SCAN_TILE)   // 147

typedef unsigned long long ull;

// ---------------- device scratch (static; no allocation allowed) -------------
__device__ __align__(16) float g_acc[(size_t)NN * DIM];   // normalized agg
__device__ __align__(16) float g_h1[(size_t)NN * DIM];
__device__ __align__(16) float g_h2[(size_t)NN * DIM];
__device__ int g_deg[SCAN_M];
__device__ int g_start[SCAN_M];
__device__ int g_cursor[SCAN_M];
__device__ int g_tilesum[SCAN_NT];
__device__ int g_sorted[EE];          // dst ids grouped by (rel,node)
__device__ int g_odd_nonzero;         // dtype probe result

// ---------------- f32x2 helpers ----------------------------------------------
__device__ __forceinline__ void fma2(ull& d, ull a, ull b) {
    asm("fma.rn.f32x2 %0, %1, %2, %3;" : "=l"(d) : "l"(a), "l"(b), "l"(d));
}
__device__ __forceinline__ float unpack_sum(ull v) {
    float lo, hi;
    asm("mov.b64 {%0, %1}, %2;" : "=f"(lo), "=f"(hi) : "l"(v));
    return lo + hi;
}

// ---------------- init: zero degrees + dtype probe (merged) ------------------
// int64 edge_type (values 0..4) => all odd 32-bit words zero.
// int32 => odd words are real values, mostly nonzero. Probe stays in-bounds
// for both interpretations (first 400000 words).
__global__ void zero_detect_kernel(const int* __restrict__ et_words) {
    int i = blockIdx.x * blockDim.x + threadIdx.x;
    int stride = gridDim.x * blockDim.x;
    for (int j = i; j < SCAN_M; j += stride) g_deg[j] = 0;
    if (i == 0) g_odd_nonzero = 0;
    int idx = 2 * i + 1;
    if (idx < 400000) {
        if (et_words[idx] != 0) atomicOr(&g_odd_nonzero, 1);
    }
}

// ---------------- CSR build: histogram ---------------------------------------
__global__ void hist_kernel(const void* __restrict__ ei_raw,
                            const void* __restrict__ et_raw) {
    const bool is64 = (g_odd_nonzero == 0);
    int e = blockIdx.x * blockDim.x + threadIdx.x;
    if (e >= EE) return;
    long long rr; int src;
    if (is64) {
        rr  = ((const long long*)et_raw)[e];
        src = (int)((const long long*)ei_raw)[e];
    } else {
        rr  = ((const int*)et_raw)[e];
        src = ((const int*)ei_raw)[e];
    }
    if (rr >= 0 && rr < NREL) atomicAdd(&g_deg[(int)rr * NN + src], 1);
}

// ---------------- CSR build: 3-kernel exclusive scan -------------------------
__global__ void scan1_kernel() {
    __shared__ int wsum[8];
    int b = blockIdx.x, t = threadIdx.x;
    int lane = t & 31, w = t >> 5;
    int base = b * SCAN_TILE + t * 4;
    int v[4];
    #pragma unroll
    for (int i = 0; i < 4; i++) {
        int idx = base + i;
        v[i] = (idx < SCAN_M) ? g_deg[idx] : 0;
    }
    int s = v[0] + v[1] + v[2] + v[3];
    int sc = s;
    #pragma unroll
    for (int o = 1; o < 32; o <<= 1) {
        int n = __shfl_up_sync(0xffffffffu, sc, o);
        if (lane >= o) sc += n;
    }
    if (lane == 31) wsum[w] = sc;
    __syncthreads();
    if (w == 0) {
        int ws = (lane < 8) ? wsum[lane] : 0;
        #pragma unroll
        for (int o = 1; o < 8; o <<= 1) {
            int n = __shfl_up_sync(0xffffffffu, ws, o);
            if (lane >= o) ws += n;
        }
        if (lane < 8) wsum[lane] = ws;
    }
    __syncthreads();
    int run = sc - s + ((w > 0) ? wsum[w - 1] : 0);
    #pragma unroll
    for (int i = 0; i < 4; i++) {
        int idx = base + i;
        if (idx < SCAN_M) g_start[idx] = run;
        run += v[i];
    }
    if (t == 255) g_tilesum[b] = run;
}

__global__ void scan2_kernel() {
    __shared__ int wsum[8];
    int t = threadIdx.x, lane = t & 31, w = t >> 5;
    int v = (t < SCAN_NT) ? g_tilesum[t] : 0;
    int sc = v;
    #pragma unroll
    for (int o = 1; o < 32; o <<= 1) {
        int n = __shfl_up_sync(0xffffffffu, sc, o);
        if (lane >= o) sc += n;
    }
    if (lane == 31) wsum[w] = sc;
    __syncthreads();
    if (w == 0) {
        int ws = (lane < 8) ? wsum[lane] : 0;
        #pragma unroll
        for (int o = 1; o < 8; o <<= 1) {
            int n = __shfl_up_sync(0xffffffffu, ws, o);
            if (lane >= o) ws += n;
        }
        if (lane < 8) wsum[lane] = ws;
    }
    __syncthreads();
    int excl = sc - v + ((w > 0) ? wsum[w - 1] : 0);
    if (t < SCAN_NT) g_tilesum[t] = excl;
}

__global__ void scan3_kernel() {
    int b = blockIdx.x;
    int off = g_tilesum[b];
    int base = b * SCAN_TILE + threadIdx.x * 4;
    #pragma unroll
    for (int i = 0; i < 4; i++) {
        int idx = base + i;
        if (idx < SCAN_M) {
            int s = g_start[idx] + off;
            g_start[idx]  = s;
            g_cursor[idx] = s;
        }
    }
}

// ---------------- CSR build: placement ---------------------------------------
__global__ void place_kernel(const void* __restrict__ ei_raw,
                             const void* __restrict__ et_raw) {
    const bool is64 = (g_odd_nonzero == 0);
    int e = blockIdx.x * blockDim.x + threadIdx.x;
    if (e >= EE) return;
    long long rr; int src, dst;
    if (is64) {
        rr  = ((const long long*)et_raw)[e];
        src = (int)((const long long*)ei_raw)[e];
        dst = (int)((const long long*)ei_raw)[EE + e];
    } else {
        rr  = ((const int*)et_raw)[e];
        src = ((const int*)ei_raw)[e];
        dst = ((const int*)ei_raw)[EE + e];
    }
    if (rr >= 0 && rr < NREL) {
        int pos = atomicAdd(&g_cursor[(int)rr * NN + src], 1);
        g_sorted[pos] = dst;
    }
}

// ---------------- gather-reduce: acc[n] = mean over edges of h[dst] ----------
__global__ void gather_kernel(int rel, const float* __restrict__ hin) {
    int lane = threadIdx.x & 31;
    int warp0 = (blockIdx.x * blockDim.x + threadIdx.x) >> 5;
    int nwarps = (gridDim.x * blockDim.x) >> 5;
    for (int gw = warp0; gw < NN; gw += nwarps) {
        int bin = rel * NN + gw;
        int st = g_start[bin];
        int d  = g_deg[bin];
        if (lane < 24) {
            float4 a = make_float4(0.f, 0.f, 0.f, 0.f);
            int dst = (d > 0) ? __ldg(&g_sorted[st]) : 0;
            for (int j = 0; j < d; j++) {
                int nd = (j + 1 < d) ? __ldg(&g_sorted[st + j + 1]) : 0;
                float4 v = __ldg((const float4*)(hin + (size_t)dst * DIM) + lane);
                a.x += v.x; a.y += v.y; a.z += v.z; a.w += v.w;
                dst = nd;
            }
            float inv = 1.f / (float)max(d, 1);
            a.x *= inv; a.y *= inv; a.z *= inv; a.w *= inv;
            *((float4*)(g_acc + (size_t)gw * DIM) + lane) = a;
        }
    }
}

// =============== f32x2 combine: relu([agg|h] @ [W;root] + b) =================
// Block (16,16). Tile = 128 nodes x 96 cols; thread = 8 nodes x 6 cols.
// K=192 packed as (k,k+1) pairs in f32x2 lanes (even/odd-k partial sums).
// SMEM: Ws  [96][194] fp32, W transposed ([c][k], pad 194 -> conflict-free)
//       As  [128][192] fp32  ([node][k])
//       bs  [96]
#define CB_WPAD  194
#define CB_WS_F  (ND * CB_WPAD)             // 18624 floats
#define CB_AS_F  (TILE_M * KD)              // 24576 floats
#define CB_SMEM  ((CB_WS_F + CB_AS_F + ND) * 4)   // 173184 bytes

__global__ __launch_bounds__(256, 1)
void combine2_kernel(const float* __restrict__ hin,
                     const float* __restrict__ W,      // [96,96] rel slice
                     const float* __restrict__ root,   // [96,96]
                     const float* __restrict__ bias,   // [96]
                     float* __restrict__ hout) {
    extern __shared__ float sm[];
    float* Ws = sm;                     // [96][194]
    float* As = sm + CB_WS_F;           // [128][192]
    float* bs = sm + CB_WS_F + CB_AS_F; // [96]

    const int tx = threadIdx.x;         // 16
    const int ty = threadIdx.y;         // 16
    const int tid = ty * 16 + tx;

    // stage W transposed: Ws[c][k] = (k<96 ? W[k][c] : root[k-96][c])
    for (int idx = tid; idx < KD * ND; idx += 256) {
        int k = idx / ND;
        int c = idx - k * ND;           // coalesced over c
        float v = (k < DIM) ? W[k * DIM + c] : root[(k - DIM) * DIM + c];
        Ws[c * CB_WPAD + k] = v;
    }
    if (tid < ND) bs[tid] = bias[tid];
    __syncthreads();

    const int ntiles = (NN + TILE_M - 1) / TILE_M;   // 391
    for (int tile = blockIdx.x; tile < ntiles; tile += gridDim.x) {
        const int base = tile * TILE_M;

        __syncthreads();   // As free from previous tile's compute
        for (int idx = tid; idx < TILE_M * KD; idx += 256) {
            int m = idx / KD;
            int k = idx - m * KD;       // coalesced over k
            int node = base + m;
            float v = 0.f;
            if (node < NN)
                v = (k < DIM) ? g_acc[(size_t)node * DIM + k]
                              : hin[(size_t)node * DIM + (k - DIM)];
            As[m * KD + k] = v;
        }
        __syncthreads();

        ull s[8][6];
        #pragma unroll
        for (int i = 0; i < 8; i++)
            #pragma unroll
            for (int j = 0; j < 6; j++) s[i][j] = 0ULL;

        #pragma unroll 2
        for (int k0 = 0; k0 < KD; k0 += 2) {
            ull w[6];
            #pragma unroll
            for (int j = 0; j < 6; j++)
                w[j] = *(const ull*)&Ws[(tx + 16 * j) * CB_WPAD + k0];
            #pragma unroll
            for (int i = 0; i < 8; i++) {
                ull a = *(const ull*)&As[(ty + 16 * i) * KD + k0];
                #pragma unroll
                for (int j = 0; j < 6; j++) fma2(s[i][j], a, w[j]);
            }
        }

        #pragma unroll
        for (int i = 0; i < 8; i++) {
            int node = base + ty + 16 * i;
            if (node < NN) {
                #pragma unroll
                for (int j = 0; j < 6; j++) {
                    int c = tx + 16 * j;
                    float v = unpack_sum(s[i][j]) + bs[c];
                    hout[(size_t)node * DIM + c] = fmaxf(v, 0.f);
                }
            }
        }
    }
}

// =============== f32x2 final linear: out = h @ lin_w + lin_b =================
// Block (16,16). Tile = 128 nodes x 64 cols; thread = 8 nodes x 4 cols.
#define FL_WPAD  98
#define FL_WS_F  (LDIM * FL_WPAD)           // 6272 floats
#define FL_AS_F  (TILE_M * DIM)             // 12288 floats
#define FL_SMEM  ((FL_WS_F + FL_AS_F + LDIM) * 4)   // 74752 bytes

__global__ __launch_bounds__(256, 2)
void final2_kernel(const float* __restrict__ hin,
                   const float* __restrict__ lw,  // [96,64]
                   const float* __restrict__ lb,  // [64]
                   float* __restrict__ out) {
    extern __shared__ float sm[];
    float* Ws = sm;                     // [64][98]
    float* As = sm + FL_WS_F;           // [128][96]
    float* bs = sm + FL_WS_F + FL_AS_F; // [64]

    const int tx = threadIdx.x;
    const int ty = threadIdx.y;
    const int tid = ty * 16 + tx;

    for (int idx = tid; idx < DIM * LDIM; idx += 256) {
        int k = idx / LDIM;
        int c = idx - k * LDIM;
        Ws[c * FL_WPAD + k] = lw[k * LDIM + c];
    }
    if (tid < LDIM) bs[tid] = lb[tid];
    __syncthreads();

    const int ntiles = (NN + TILE_M - 1) / TILE_M;
    for (int tile = blockIdx.x; tile < ntiles; tile += gridDim.x) {
        const int base = tile * TILE_M;

        __syncthreads();
        for (int idx = tid; idx < TILE_M * DIM; idx += 256) {
            int m = idx / DIM;
            int k = idx - m * DIM;
            int node = base + m;
            As[m * DIM + k] = (node < NN) ? hin[(size_t)node * DIM + k] : 0.f;
        }
        __syncthreads();

        ull s[8][4];
        #pragma unroll
        for (int i = 0; i < 8; i++)
            #pragma unroll
            for (int j = 0; j < 4; j++) s[i][j] = 0ULL;

        #pragma unroll 4
        for (int k0 = 0; k0 < DIM; k0 += 2) {
            ull w[4];
            #pragma unroll
            for (int j = 0; j < 4; j++)
                w[j] = *(const ull*)&Ws[(tx + 16 * j) * FL_WPAD + k0];
            #pragma unroll
            for (int i = 0; i < 8; i++) {
                ull a = *(const ull*)&As[(ty + 16 * i) * DIM + k0];
                #pragma unroll
                for (int j = 0; j < 4; j++) fma2(s[i][j], a, w[j]);
            }
        }

        #pragma unroll
        for (int i = 0; i < 8; i++) {
            int node = base + ty + 16 * i;
            if (node < NN) {
                #pragma unroll
                for (int j = 0; j < 4; j++) {
                    int c = tx + 16 * j;
                    out[(size_t)node * LDIM + c] = unpack_sum(s[i][j]) + bs[c];
                }
            }
        }
    }
}

// ---------------- launch -----------------------------------------------------
extern "C" void kernel_launch(void* const* d_in, const int* in_sizes, int n_in,
                              void* d_out, int out_size) {
    const float* x      = (const float*)d_in[0];
    const void*  ei     = d_in[1];                  // int32 or int64 (probed)
    const void*  et     = d_in[2];                  // int32 or int64 (probed)
    const float* w1     = (const float*)d_in[3];    // [5,96,96]
    const float* root1  = (const float*)d_in[4];    // [96,96]
    const float* b1     = (const float*)d_in[5];    // [96]
    const float* w2     = (const float*)d_in[6];    // [5,96,96]
    const float* root2  = (const float*)d_in[7];    // [96,96]
    const float* b2     = (const float*)d_in[8];    // [96]
    const float* lin_w  = (const float*)d_in[9];    // [96,64]
    const float* lin_b  = (const float*)d_in[10];   // [64]
    float*       out    = (float*)d_out;

    float *h1, *h2;
    cudaGetSymbolAddress((void**)&h1, g_h1);
    cudaGetSymbolAddress((void**)&h2, g_h2);

    cudaFuncSetAttribute(combine2_kernel,
                         cudaFuncAttributeMaxDynamicSharedMemorySize, CB_SMEM);
    cudaFuncSetAttribute(final2_kernel,
                         cudaFuncAttributeMaxDynamicSharedMemorySize, FL_SMEM);

    dim3 tcBlock(16, 16);
    const int cbGrid = 148;         // 1 block/SM (169 KB smem)
    const int flGrid = 296;         // 2 blocks/SM (73 KB smem)
    const int gatherGrid = 1184;    // resident: 148 SM x 8 blocks (256 thr)

    // ---- CSR build (once per call) ----
    zero_detect_kernel<<<782, 256>>>((const int*)et);
    hist_kernel<<<(EE + 255) / 256, 256>>>(ei, et);
    scan1_kernel<<<SCAN_NT, 256>>>();
    scan2_kernel<<<1, 256>>>();
    scan3_kernel<<<SCAN_NT, 256>>>();
    place_kernel<<<(EE + 255) / 256, 256>>>(ei, et);

    // ---- layer 0: rel 0, x -> h1 ----
    gather_kernel<<<gatherGrid, 256>>>(0, x);
    combine2_kernel<<<cbGrid, tcBlock, CB_SMEM>>>(x, w1, root1, b1, h1);

    // ---- layer 1: rel 1, h1 -> h2 ----
    gather_kernel<<<gatherGrid, 256>>>(1, h1);
    combine2_kernel<<<cbGrid, tcBlock, CB_SMEM>>>(
        h1, w2 + (size_t)1 * DIM * DIM, root2, b2, h2);

    // ---- layer 2: rel 2, h2 -> h1 ----
    gather_kernel<<<gatherGrid, 256>>>(2, h2);
    combine2_kernel<<<cbGrid, tcBlock, CB_SMEM>>>(
        h2, w2 + (size_t)2 * DIM * DIM, root2, b2, h1);

    // ---- final linear: h1 -> out ----
    final2_kernel<<<flGrid, tcBlock, FL_SMEM>>>(h1, lin_w, lin_b, out);
}